// round 15
// baseline (speedup 1.0000x reference)
#include <cuda_runtime.h>
#include <cuda_fp16.h>
#include <cstdint>

#define N_NODES 50000
#define N_EDGES 800000
#define D 64

// -------- device scratch (zero-initialized; no allocations allowed) --------
__device__ __half g_node16[N_NODES * D];   // fp16 (embed * outdeg)       6.4 MB
__device__ __half g_acc16[N_NODES * D];    // fp16 N_h * indeg (atomic)   6.4 MB

// ---------------------------------------------------------------------------
// 1. prep: node16 = fp16(embed * outdeg), and zero acc16.
//    400K threads; thread t handles 8 consecutive elems (one outdeg row
//    covers them: 8 | 64) and zeroes 16B of acc16.
// ---------------------------------------------------------------------------
__global__ void prep_kernel(const float* __restrict__ embed,
                            const float* __restrict__ outdeg) {
    int t = blockIdx.x * blockDim.x + threadIdx.x;
    if (t >= N_EDGES / 2) return;   // 400K = (N_NODES*D)/8

    float4 v0 = __ldg((const float4*)embed + 2 * t);
    float4 v1 = __ldg((const float4*)embed + 2 * t + 1);
    float od = __ldg(&outdeg[t >> 3]);
    __half2 h0 = __floats2half2_rn(v0.x * od, v0.y * od);
    __half2 h1 = __floats2half2_rn(v0.z * od, v0.w * od);
    __half2 h2 = __floats2half2_rn(v1.x * od, v1.y * od);
    __half2 h3 = __floats2half2_rn(v1.z * od, v1.w * od);
    uint4 pk;
    pk.x = *reinterpret_cast<uint32_t*>(&h0);
    pk.y = *reinterpret_cast<uint32_t*>(&h1);
    pk.z = *reinterpret_cast<uint32_t*>(&h2);
    pk.w = *reinterpret_cast<uint32_t*>(&h3);
    ((uint4*)g_node16)[t] = pk;

    ((uint4*)g_acc16)[t] = make_uint4(0u, 0u, 0u, 0u);
}

// ---------------------------------------------------------------------------
// 2. edge kernel: 8 lanes per edge. Lane c handles 8 halves (16B) of the row.
//    msg = node16[src] * (ew * indeg[dst]) ; acc16[dst] += msg via one
//    red.global.add.noftz.v4.f16x2 (8 halves per op -> 6.4M ops total).
// ---------------------------------------------------------------------------
__global__ void edge_kernel(const int* __restrict__ src,
                            const int* __restrict__ dst,
                            const float* __restrict__ ew,
                            const float* __restrict__ indeg) {
    int gid = blockIdx.x * blockDim.x + threadIdx.x;
    if (gid >= N_EDGES * 8) return;
    int e = gid >> 3;
    int c = gid & 7;

    int s = __ldg(&src[e]);
    int d = __ldg(&dst[e]);
    float w = __ldg(&ew[e]) * __ldg(&indeg[d]);
    __half2 w2 = __half2half2(__float2half_rn(w));

    uint4 hv = __ldg((const uint4*)g_node16 + (size_t)s * 8 + c);
    __half2 m0 = __hmul2(*reinterpret_cast<__half2*>(&hv.x), w2);
    __half2 m1 = __hmul2(*reinterpret_cast<__half2*>(&hv.y), w2);
    __half2 m2 = __hmul2(*reinterpret_cast<__half2*>(&hv.z), w2);
    __half2 m3 = __hmul2(*reinterpret_cast<__half2*>(&hv.w), w2);
    uint32_t u0 = *reinterpret_cast<uint32_t*>(&m0);
    uint32_t u1 = *reinterpret_cast<uint32_t*>(&m1);
    uint32_t u2 = *reinterpret_cast<uint32_t*>(&m2);
    uint32_t u3 = *reinterpret_cast<uint32_t*>(&m3);

    __half* ap = g_acc16 + (size_t)d * D + c * 8;
    asm volatile("red.global.add.noftz.v4.f16x2 [%0], {%1, %2, %3, %4};"
                 :: "l"(ap), "r"(u0), "r"(u1), "r"(u2), "r"(u3)
                 : "memory");
}

// ---------------------------------------------------------------------------
// 3. out = LeakyReLU((embed + acc16) @ W^T + b)   [acc16 = N_h*indeg]
//    Tiled GEMM: 128 rows x 64 cols per block, 128 threads, 8x8/thread,
//    packed fma.rn.f32x2. (Proven structure; tile load adds the acc16 cvt.)
// ---------------------------------------------------------------------------
typedef unsigned long long ull;
__device__ __forceinline__ ull fma_f2(ull a, ull b, ull c) {
    ull d;
    asm("fma.rn.f32x2 %0, %1, %2, %3;" : "=l"(d) : "l"(a), "l"(b), "l"(c));
    return d;
}
__device__ __forceinline__ ull pack_f2(float lo, float hi) {
    ull r;
    asm("mov.b64 %0, {%1, %2};" : "=l"(r) : "f"(lo), "f"(hi));
    return r;
}
__device__ __forceinline__ void unpack_f2(ull v, float& lo, float& hi) {
    asm("mov.b64 {%0, %1}, %2;" : "=f"(lo), "=f"(hi) : "l"(v));
}

#define OB_ROWS 128

__global__ void __launch_bounds__(128) out_kernel(const float* __restrict__ embed,
                                                  const float* __restrict__ W,
                                                  const float* __restrict__ b,
                                                  float* __restrict__ out) {
    __shared__ float xs[OB_ROWS][D + 1];
    __shared__ float Wt[D][D];
    __shared__ float bs[D];

    int tid = threadIdx.x;

    for (int i = tid; i < D * D; i += 128) {
        int j = i >> 6, k = i & 63;
        Wt[k][j] = W[i];
    }
    if (tid < D) bs[tid] = b[tid];

    int row0 = blockIdx.x * OB_ROWS;
    for (int i = tid; i < OB_ROWS * (D / 4); i += 128) {
        int r = i >> 4, q = i & 15;          // q = float4 index within row
        int gr = row0 + r;
        int grc = gr < N_NODES ? gr : N_NODES - 1;
        float4 e = __ldg((const float4*)(embed + (size_t)grc * D) + q);
        uint2 a = *((const uint2*)g_acc16 + (size_t)grc * 16 + q);
        float2 f0 = __half22float2(*(__half2*)&a.x);
        float2 f1 = __half22float2(*(__half2*)&a.y);
        xs[r][q * 4 + 0] = e.x + f0.x;
        xs[r][q * 4 + 1] = e.y + f0.y;
        xs[r][q * 4 + 2] = e.z + f1.x;
        xs[r][q * 4 + 3] = e.w + f1.y;
    }
    __syncthreads();

    int tx = tid & 7;        // col octet
    int ty = tid >> 3;       // row octet

    ull acc[8][4];
    {
        ulonglong2 b01 = *(const ulonglong2*)&bs[tx * 8];
        ulonglong2 b23 = *(const ulonglong2*)&bs[tx * 8 + 4];
#pragma unroll
        for (int rr = 0; rr < 8; rr++) {
            acc[rr][0] = b01.x; acc[rr][1] = b01.y;
            acc[rr][2] = b23.x; acc[rr][3] = b23.y;
        }
    }

#pragma unroll 4
    for (int k = 0; k < D; k++) {
        ulonglong2 w01 = *(const ulonglong2*)&Wt[k][tx * 8];
        ulonglong2 w23 = *(const ulonglong2*)&Wt[k][tx * 8 + 4];
#pragma unroll
        for (int rr = 0; rr < 8; rr++) {
            float xv = xs[ty * 8 + rr][k];
            ull xp = pack_f2(xv, xv);
            acc[rr][0] = fma_f2(xp, w01.x, acc[rr][0]);
            acc[rr][1] = fma_f2(xp, w01.y, acc[rr][1]);
            acc[rr][2] = fma_f2(xp, w23.x, acc[rr][2]);
            acc[rr][3] = fma_f2(xp, w23.y, acc[rr][3]);
        }
    }

#pragma unroll
    for (int rr = 0; rr < 8; rr++) {
        int gr = row0 + ty * 8 + rr;
        if (gr < N_NODES) {
            float o[8];
#pragma unroll
            for (int p = 0; p < 4; p++) unpack_f2(acc[rr][p], o[2 * p], o[2 * p + 1]);
#pragma unroll
            for (int q = 0; q < 8; q++) o[q] = o[q] > 0.f ? o[q] : 0.01f * o[q];
            float* dst = out + (size_t)gr * D + tx * 8;
            ((float4*)dst)[0] = make_float4(o[0], o[1], o[2], o[3]);
            ((float4*)dst)[1] = make_float4(o[4], o[5], o[6], o[7]);
        }
    }
}

// ---------------------------------------------------------------------------
// kernel_launch — 3 launches
// ---------------------------------------------------------------------------
extern "C" void kernel_launch(void* const* d_in, const int* in_sizes, int n_in,
                              void* d_out, int out_size) {
    const float* embed  = (const float*)d_in[0];
    const int*   src    = (const int*)d_in[1];
    const int*   dst    = (const int*)d_in[2];
    const float* ew     = (const float*)d_in[3];
    const float* outdeg = (const float*)d_in[4];
    const float* indeg  = (const float*)d_in[5];
    const float* W      = (const float*)d_in[6];
    const float* b      = (const float*)d_in[7];
    float* out = (float*)d_out;

    {   // 1. fp16 node prep + acc16 zero
        int threads = 256;
        int blocks = (N_EDGES / 2 + threads - 1) / threads;   // 1563
        prep_kernel<<<blocks, threads>>>(embed, outdeg);
    }
    {   // 2. edge scatter-add via vector fp16 atomics (8 lanes/edge)
        int threads = 256;
        long long total = (long long)N_EDGES * 8;             // 6.4M
        int blocks = (int)((total + threads - 1) / threads);  // 25000
        edge_kernel<<<blocks, threads>>>(src, dst, ew, indeg);
    }
    {   // 3. tiled GEMM + LeakyReLU (x = embed + acc16)
        int blocks = (N_NODES + OB_ROWS - 1) / OB_ROWS;       // 391
        out_kernel<<<blocks, 128>>>(embed, W, b, out);
    }
}

// round 16
// speedup vs baseline: 1.3475x; 1.3475x over previous
#include <cuda_runtime.h>
#include <cuda_fp16.h>
#include <cstdint>

#define N_NODES 50000
#define N_EDGES 800000
#define D 64
#define CAP 64

// -------- device scratch (zero-initialized; no allocations allowed) --------
__device__ __half   g_node16[N_NODES * D];     // fp16 (embed * outdeg)   6.4 MB
__device__ float    g_acc[N_NODES * D];        // fp32 embed + N_h*indeg 12.8 MB
__device__ int      g_cnt[N_NODES];            // bucket cursors
__device__ uint32_t g_edges[N_NODES * CAP];    // (src<<16)|fp16(ew)     12.8 MB
__device__ uint4    g_ovf[4096];               // overflow (src,dst,w32,-)
__device__ int      g_ovf_cnt;

// ---------------------------------------------------------------------------
// 1. fused prep + scatter, 2 edges / 8 prep-elems per thread (400K threads).
// ---------------------------------------------------------------------------
__global__ void prep_scatter_kernel(const float* __restrict__ embed,
                                    const int* __restrict__ src,
                                    const int* __restrict__ dst,
                                    const float* __restrict__ ew,
                                    const float* __restrict__ outdeg) {
    int t = blockIdx.x * blockDim.x + threadIdx.x;
    if (t >= N_EDGES / 2) return;

    // ---- prep: 8 consecutive elems (one outdeg row covers them) ----
    {
        float4 v0 = __ldg((const float4*)embed + 2 * t);
        float4 v1 = __ldg((const float4*)embed + 2 * t + 1);
        float od = __ldg(&outdeg[t >> 3]);
        __half2 h0 = __floats2half2_rn(v0.x * od, v0.y * od);
        __half2 h1 = __floats2half2_rn(v0.z * od, v0.w * od);
        __half2 h2 = __floats2half2_rn(v1.x * od, v1.y * od);
        __half2 h3 = __floats2half2_rn(v1.z * od, v1.w * od);
        uint4 pk;
        pk.x = *reinterpret_cast<uint32_t*>(&h0);
        pk.y = *reinterpret_cast<uint32_t*>(&h1);
        pk.z = *reinterpret_cast<uint32_t*>(&h2);
        pk.w = *reinterpret_cast<uint32_t*>(&h3);
        ((uint4*)g_node16)[t] = pk;
    }

    // ---- scatter 2 edges (independent chains) ----
    {
        int2   s2 = ((const int2*)src)[t];
        int2   d2 = ((const int2*)dst)[t];
        float2 w2 = ((const float2*)ew)[t];

        uint32_t rec0 = ((uint32_t)s2.x << 16) |
                        (uint32_t)__half_as_ushort(__float2half_rn(w2.x));
        uint32_t rec1 = ((uint32_t)s2.y << 16) |
                        (uint32_t)__half_as_ushort(__float2half_rn(w2.y));

        int pos0 = atomicAdd(&g_cnt[d2.x], 1);
        int pos1 = atomicAdd(&g_cnt[d2.y], 1);

        if (pos0 < CAP) {
            g_edges[d2.x * CAP + pos0] = rec0;
        } else {
            int op = atomicAdd(&g_ovf_cnt, 1);
            if (op < 4096)
                g_ovf[op] = make_uint4((unsigned)s2.x, (unsigned)d2.x,
                                       __float_as_uint(w2.x), 0u);
        }
        if (pos1 < CAP) {
            g_edges[d2.y * CAP + pos1] = rec1;
        } else {
            int op = atomicAdd(&g_ovf_cnt, 1);
            if (op < 4096)
                g_ovf[op] = make_uint4((unsigned)s2.y, (unsigned)d2.y,
                                       __float_as_uint(w2.y), 0u);
        }
    }
}

// ---------------------------------------------------------------------------
// 2. accumulate: 8 lanes per node. 16-record rounds: both record words loaded
//    up-front, then all gathers issue back-to-back (MLP~16, one dep level).
//    Writes embed + N_h*indeg (out_kernel reads one stream). Resets g_cnt.
// ---------------------------------------------------------------------------
__global__ void accum_kernel(const float* __restrict__ embed,
                             const float* __restrict__ indeg) {
    int gid = blockIdx.x * blockDim.x + threadIdx.x;
    int n = gid >> 3;
    if (n >= N_NODES) return;
    int c = gid & 7;
    unsigned gmask = 0xFFu << (threadIdx.x & 24);  // this 8-lane group

    int cntr = g_cnt[n];
    int cnt = cntr < CAP ? cntr : CAP;
    const uint32_t* bucket = g_edges + (size_t)n * CAP;

    float2 a0 = make_float2(0.f, 0.f), a1 = a0, a2 = a0, a3 = a0;

    for (int base = 0; base < cnt; base += 16) {
        uint32_t r0 = 0, r1 = 0;
        if (base + c < cnt)     r0 = __ldg(&bucket[base + c]);
        if (base + 8 + c < cnt) r1 = __ldg(&bucket[base + 8 + c]);
        int rem = cnt - base;
#pragma unroll
        for (int i = 0; i < 16; i++) {
            if (i < rem) {
                uint32_t rec = __shfl_sync(gmask, (i < 8) ? r0 : r1, i & 7, 8);
                float w = __half2float(__ushort_as_half(
                              (unsigned short)(rec & 0xFFFFu)));
                uint4 hv = __ldg((const uint4*)(g_node16 +
                              (size_t)(rec >> 16) * D) + c);
                float2 f0 = __half22float2(*(__half2*)&hv.x);
                float2 f1 = __half22float2(*(__half2*)&hv.y);
                float2 f2 = __half22float2(*(__half2*)&hv.z);
                float2 f3 = __half22float2(*(__half2*)&hv.w);
                a0.x = fmaf(f0.x, w, a0.x); a0.y = fmaf(f0.y, w, a0.y);
                a1.x = fmaf(f1.x, w, a1.x); a1.y = fmaf(f1.y, w, a1.y);
                a2.x = fmaf(f2.x, w, a2.x); a2.y = fmaf(f2.y, w, a2.y);
                a3.x = fmaf(f3.x, w, a3.x); a3.y = fmaf(f3.y, w, a3.y);
            }
        }
    }

    // overflow fallback (effectively never taken)
    if (cntr > CAP) {
        int m = g_ovf_cnt; if (m > 4096) m = 4096;
        for (int i = 0; i < m; i++) {
            uint4 rec = g_ovf[i];
            if ((int)rec.y == n) {
                float w = __uint_as_float(rec.z);
                uint4 hv = __ldg((const uint4*)(g_node16 +
                              (size_t)rec.x * D) + c);
                float2 f0 = __half22float2(*(__half2*)&hv.x);
                float2 f1 = __half22float2(*(__half2*)&hv.y);
                float2 f2 = __half22float2(*(__half2*)&hv.z);
                float2 f3 = __half22float2(*(__half2*)&hv.w);
                a0.x = fmaf(f0.x, w, a0.x); a0.y = fmaf(f0.y, w, a0.y);
                a1.x = fmaf(f1.x, w, a1.x); a1.y = fmaf(f1.y, w, a1.y);
                a2.x = fmaf(f2.x, w, a2.x); a2.y = fmaf(f2.y, w, a2.y);
                a3.x = fmaf(f3.x, w, a3.x); a3.y = fmaf(f3.y, w, a3.y);
            }
        }
    }

    float ind = __ldg(&indeg[n]);
    float4 e0 = __ldg((const float4*)(embed + (size_t)n * D) + 2 * c);
    float4 e1 = __ldg((const float4*)(embed + (size_t)n * D) + 2 * c + 1);
    float* op = g_acc + (size_t)n * D + c * 8;
    ((float4*)op)[0] = make_float4(e0.x + a0.x * ind, e0.y + a0.y * ind,
                                   e0.z + a1.x * ind, e0.w + a1.y * ind);
    ((float4*)op)[1] = make_float4(e1.x + a2.x * ind, e1.y + a2.y * ind,
                                   e1.z + a3.x * ind, e1.w + a3.y * ind);

    if (c == 0) g_cnt[n] = 0;   // reset for next replay
}

// ---------------------------------------------------------------------------
// 3. out = LeakyReLU(g_acc @ W^T + b)   [g_acc = embed + N_h*indeg]
//    Tiled GEMM: 128 rows x 64 cols per block, 128 threads, 8x8/thread,
//    packed fma.rn.f32x2.
// ---------------------------------------------------------------------------
typedef unsigned long long ull;
__device__ __forceinline__ ull fma_f2(ull a, ull b, ull c) {
    ull d;
    asm("fma.rn.f32x2 %0, %1, %2, %3;" : "=l"(d) : "l"(a), "l"(b), "l"(c));
    return d;
}
__device__ __forceinline__ ull pack_f2(float lo, float hi) {
    ull r;
    asm("mov.b64 %0, {%1, %2};" : "=l"(r) : "f"(lo), "f"(hi));
    return r;
}
__device__ __forceinline__ void unpack_f2(ull v, float& lo, float& hi) {
    asm("mov.b64 {%0, %1}, %2;" : "=f"(lo), "=f"(hi) : "l"(v));
}

#define OB_ROWS 128

__global__ void __launch_bounds__(128) out_kernel(const float* __restrict__ W,
                                                  const float* __restrict__ b,
                                                  float* __restrict__ out) {
    __shared__ float xs[OB_ROWS][D + 1];
    __shared__ float Wt[D][D];
    __shared__ float bs[D];

    int tid = threadIdx.x;
    if (blockIdx.x == 0 && tid == 0) g_ovf_cnt = 0;   // reset for next replay

    for (int i = tid; i < D * D; i += 128) {
        int j = i >> 6, k = i & 63;
        Wt[k][j] = W[i];
    }
    if (tid < D) bs[tid] = b[tid];

    int row0 = blockIdx.x * OB_ROWS;
    for (int i = tid; i < OB_ROWS * (D / 4); i += 128) {
        int r = i >> 4, q = i & 15;
        int gr = row0 + r;
        int grc = gr < N_NODES ? gr : N_NODES - 1;
        float4 a = *((const float4*)(g_acc + (size_t)grc * D) + q);
        xs[r][q * 4 + 0] = a.x;
        xs[r][q * 4 + 1] = a.y;
        xs[r][q * 4 + 2] = a.z;
        xs[r][q * 4 + 3] = a.w;
    }
    __syncthreads();

    int tx = tid & 7;        // col octet
    int ty = tid >> 3;       // row octet

    ull acc[8][4];
    {
        ulonglong2 b01 = *(const ulonglong2*)&bs[tx * 8];
        ulonglong2 b23 = *(const ulonglong2*)&bs[tx * 8 + 4];
#pragma unroll
        for (int rr = 0; rr < 8; rr++) {
            acc[rr][0] = b01.x; acc[rr][1] = b01.y;
            acc[rr][2] = b23.x; acc[rr][3] = b23.y;
        }
    }

#pragma unroll 4
    for (int k = 0; k < D; k++) {
        ulonglong2 w01 = *(const ulonglong2*)&Wt[k][tx * 8];
        ulonglong2 w23 = *(const ulonglong2*)&Wt[k][tx * 8 + 4];
#pragma unroll
        for (int rr = 0; rr < 8; rr++) {
            float xv = xs[ty * 8 + rr][k];
            ull xp = pack_f2(xv, xv);
            acc[rr][0] = fma_f2(xp, w01.x, acc[rr][0]);
            acc[rr][1] = fma_f2(xp, w01.y, acc[rr][1]);
            acc[rr][2] = fma_f2(xp, w23.x, acc[rr][2]);
            acc[rr][3] = fma_f2(xp, w23.y, acc[rr][3]);
        }
    }

#pragma unroll
    for (int rr = 0; rr < 8; rr++) {
        int gr = row0 + ty * 8 + rr;
        if (gr < N_NODES) {
            float o[8];
#pragma unroll
            for (int p = 0; p < 4; p++) unpack_f2(acc[rr][p], o[2 * p], o[2 * p + 1]);
#pragma unroll
            for (int q = 0; q < 8; q++) o[q] = o[q] > 0.f ? o[q] : 0.01f * o[q];
            float* dst = out + (size_t)gr * D + tx * 8;
            ((float4*)dst)[0] = make_float4(o[0], o[1], o[2], o[3]);
            ((float4*)dst)[1] = make_float4(o[4], o[5], o[6], o[7]);
        }
    }
}

// ---------------------------------------------------------------------------
// kernel_launch — 3 launches
// ---------------------------------------------------------------------------
extern "C" void kernel_launch(void* const* d_in, const int* in_sizes, int n_in,
                              void* d_out, int out_size) {
    const float* embed  = (const float*)d_in[0];
    const int*   src    = (const int*)d_in[1];
    const int*   dst    = (const int*)d_in[2];
    const float* ew     = (const float*)d_in[3];
    const float* outdeg = (const float*)d_in[4];
    const float* indeg  = (const float*)d_in[5];
    const float* W      = (const float*)d_in[6];
    const float* b      = (const float*)d_in[7];
    float* out = (float*)d_out;

    {   // 1. fused fp16 prep + bucket scatter (2 edges/thread)
        int threads = 256;
        int blocks = (N_EDGES / 2 + threads - 1) / threads;   // 1563
        prep_scatter_kernel<<<blocks, threads>>>(embed, src, dst, ew, outdeg);
    }
    {   // 2. gather-accumulate (8 lanes/node, fused embed add)
        int total = N_NODES * 8;
        int threads = 256;
        int blocks = (total + threads - 1) / threads;         // 1563
        accum_kernel<<<blocks, threads>>>(embed, indeg);
    }
    {   // 3. tiled GEMM + LeakyReLU
        int blocks = (N_NODES + OB_ROWS - 1) / OB_ROWS;       // 391
        out_kernel<<<blocks, 128>>>(W, b, out);
    }
}

// round 17
// speedup vs baseline: 1.3542x; 1.0050x over previous
#include <cuda_runtime.h>
#include <cuda_fp16.h>
#include <cstdint>

#define N_NODES 50000
#define N_EDGES 800000
#define D 64
#define CAP 64

// -------- device scratch (zero-initialized; no allocations allowed) --------
__device__ __half   g_node16[N_NODES * D];     // fp16 (embed * outdeg)   6.4 MB
__device__ float    g_acc[N_NODES * D];        // fp32 embed + N_h*indeg 12.8 MB
__device__ int      g_cnt[N_NODES];            // bucket cursors
__device__ uint32_t g_edges[N_NODES * CAP];    // (src<<16)|fp16(ew)     12.8 MB
__device__ uint4    g_ovf[4096];               // overflow (src,dst,w32,-)
__device__ int      g_ovf_cnt;

// ---------------------------------------------------------------------------
// 1. fused prep + scatter, 2 edges / 8 prep-elems per thread (400K threads).
// ---------------------------------------------------------------------------
__global__ void prep_scatter_kernel(const float* __restrict__ embed,
                                    const int* __restrict__ src,
                                    const int* __restrict__ dst,
                                    const float* __restrict__ ew,
                                    const float* __restrict__ outdeg) {
    int t = blockIdx.x * blockDim.x + threadIdx.x;
    if (t >= N_EDGES / 2) return;

    // ---- prep: 8 consecutive elems (one outdeg row covers them) ----
    {
        float4 v0 = __ldg((const float4*)embed + 2 * t);
        float4 v1 = __ldg((const float4*)embed + 2 * t + 1);
        float od = __ldg(&outdeg[t >> 3]);
        __half2 h0 = __floats2half2_rn(v0.x * od, v0.y * od);
        __half2 h1 = __floats2half2_rn(v0.z * od, v0.w * od);
        __half2 h2 = __floats2half2_rn(v1.x * od, v1.y * od);
        __half2 h3 = __floats2half2_rn(v1.z * od, v1.w * od);
        uint4 pk;
        pk.x = *reinterpret_cast<uint32_t*>(&h0);
        pk.y = *reinterpret_cast<uint32_t*>(&h1);
        pk.z = *reinterpret_cast<uint32_t*>(&h2);
        pk.w = *reinterpret_cast<uint32_t*>(&h3);
        ((uint4*)g_node16)[t] = pk;
    }

    // ---- scatter 2 edges (independent chains) ----
    {
        int2   s2 = ((const int2*)src)[t];
        int2   d2 = ((const int2*)dst)[t];
        float2 w2 = ((const float2*)ew)[t];

        uint32_t rec0 = ((uint32_t)s2.x << 16) |
                        (uint32_t)__half_as_ushort(__float2half_rn(w2.x));
        uint32_t rec1 = ((uint32_t)s2.y << 16) |
                        (uint32_t)__half_as_ushort(__float2half_rn(w2.y));

        int pos0 = atomicAdd(&g_cnt[d2.x], 1);
        int pos1 = atomicAdd(&g_cnt[d2.y], 1);

        if (pos0 < CAP) {
            g_edges[d2.x * CAP + pos0] = rec0;
        } else {
            int op = atomicAdd(&g_ovf_cnt, 1);
            if (op < 4096)
                g_ovf[op] = make_uint4((unsigned)s2.x, (unsigned)d2.x,
                                       __float_as_uint(w2.x), 0u);
        }
        if (pos1 < CAP) {
            g_edges[d2.y * CAP + pos1] = rec1;
        } else {
            int op = atomicAdd(&g_ovf_cnt, 1);
            if (op < 4096)
                g_ovf[op] = make_uint4((unsigned)s2.y, (unsigned)d2.y,
                                       __float_as_uint(w2.y), 0u);
        }
    }
}

// ---------------------------------------------------------------------------
// 2. accumulate: 8 lanes per node. 16-record rounds: both record words loaded
//    up-front, then all gathers issue back-to-back (MLP~16, one dep level).
//    Writes embed + N_h*indeg (out_kernel reads one stream). Resets g_cnt.
// ---------------------------------------------------------------------------
__global__ void accum_kernel(const float* __restrict__ embed,
                             const float* __restrict__ indeg) {
    int gid = blockIdx.x * blockDim.x + threadIdx.x;
    int n = gid >> 3;
    if (n >= N_NODES) return;
    int c = gid & 7;
    unsigned gmask = 0xFFu << (threadIdx.x & 24);  // this 8-lane group

    int cntr = g_cnt[n];
    int cnt = cntr < CAP ? cntr : CAP;
    const uint32_t* bucket = g_edges + (size_t)n * CAP;

    float2 a0 = make_float2(0.f, 0.f), a1 = a0, a2 = a0, a3 = a0;

    for (int base = 0; base < cnt; base += 16) {
        uint32_t r0 = 0, r1 = 0;
        if (base + c < cnt)     r0 = __ldg(&bucket[base + c]);
        if (base + 8 + c < cnt) r1 = __ldg(&bucket[base + 8 + c]);
        int rem = cnt - base;
#pragma unroll
        for (int i = 0; i < 16; i++) {
            if (i < rem) {
                uint32_t rec = __shfl_sync(gmask, (i < 8) ? r0 : r1, i & 7, 8);
                float w = __half2float(__ushort_as_half(
                              (unsigned short)(rec & 0xFFFFu)));
                uint4 hv = __ldg((const uint4*)(g_node16 +
                              (size_t)(rec >> 16) * D) + c);
                float2 f0 = __half22float2(*(__half2*)&hv.x);
                float2 f1 = __half22float2(*(__half2*)&hv.y);
                float2 f2 = __half22float2(*(__half2*)&hv.z);
                float2 f3 = __half22float2(*(__half2*)&hv.w);
                a0.x = fmaf(f0.x, w, a0.x); a0.y = fmaf(f0.y, w, a0.y);
                a1.x = fmaf(f1.x, w, a1.x); a1.y = fmaf(f1.y, w, a1.y);
                a2.x = fmaf(f2.x, w, a2.x); a2.y = fmaf(f2.y, w, a2.y);
                a3.x = fmaf(f3.x, w, a3.x); a3.y = fmaf(f3.y, w, a3.y);
            }
        }
    }

    // overflow fallback (effectively never taken)
    if (cntr > CAP) {
        int m = g_ovf_cnt; if (m > 4096) m = 4096;
        for (int i = 0; i < m; i++) {
            uint4 rec = g_ovf[i];
            if ((int)rec.y == n) {
                float w = __uint_as_float(rec.z);
                uint4 hv = __ldg((const uint4*)(g_node16 +
                              (size_t)rec.x * D) + c);
                float2 f0 = __half22float2(*(__half2*)&hv.x);
                float2 f1 = __half22float2(*(__half2*)&hv.y);
                float2 f2 = __half22float2(*(__half2*)&hv.z);
                float2 f3 = __half22float2(*(__half2*)&hv.w);
                a0.x = fmaf(f0.x, w, a0.x); a0.y = fmaf(f0.y, w, a0.y);
                a1.x = fmaf(f1.x, w, a1.x); a1.y = fmaf(f1.y, w, a1.y);
                a2.x = fmaf(f2.x, w, a2.x); a2.y = fmaf(f2.y, w, a2.y);
                a3.x = fmaf(f3.x, w, a3.x); a3.y = fmaf(f3.y, w, a3.y);
            }
        }
    }

    float ind = __ldg(&indeg[n]);
    float4 e0 = __ldg((const float4*)(embed + (size_t)n * D) + 2 * c);
    float4 e1 = __ldg((const float4*)(embed + (size_t)n * D) + 2 * c + 1);
    float* op = g_acc + (size_t)n * D + c * 8;
    ((float4*)op)[0] = make_float4(e0.x + a0.x * ind, e0.y + a0.y * ind,
                                   e0.z + a1.x * ind, e0.w + a1.y * ind);
    ((float4*)op)[1] = make_float4(e1.x + a2.x * ind, e1.y + a2.y * ind,
                                   e1.z + a3.x * ind, e1.w + a3.y * ind);

    if (c == 0) g_cnt[n] = 0;   // reset for next replay
}

// ---------------------------------------------------------------------------
// 3. out = LeakyReLU(g_acc @ W^T + b)   [g_acc = embed + N_h*indeg]
//    Tiled GEMM: 128 rows x 64 cols per block, 128 threads, 8x8/thread,
//    packed fma.rn.f32x2.
// ---------------------------------------------------------------------------
typedef unsigned long long ull;
__device__ __forceinline__ ull fma_f2(ull a, ull b, ull c) {
    ull d;
    asm("fma.rn.f32x2 %0, %1, %2, %3;" : "=l"(d) : "l"(a), "l"(b), "l"(c));
    return d;
}
__device__ __forceinline__ ull pack_f2(float lo, float hi) {
    ull r;
    asm("mov.b64 %0, {%1, %2};" : "=l"(r) : "f"(lo), "f"(hi));
    return r;
}
__device__ __forceinline__ void unpack_f2(ull v, float& lo, float& hi) {
    asm("mov.b64 {%0, %1}, %2;" : "=f"(lo), "=f"(hi) : "l"(v));
}

#define OB_ROWS 128

__global__ void __launch_bounds__(128) out_kernel(const float* __restrict__ W,
                                                  const float* __restrict__ b,
                                                  float* __restrict__ out) {
    __shared__ float xs[OB_ROWS][D + 1];
    __shared__ float Wt[D][D];
    __shared__ float bs[D];

    int tid = threadIdx.x;
    if (blockIdx.x == 0 && tid == 0) g_ovf_cnt = 0;   // reset for next replay

    for (int i = tid; i < D * D; i += 128) {
        int j = i >> 6, k = i & 63;
        Wt[k][j] = W[i];
    }
    if (tid < D) bs[tid] = b[tid];

    int row0 = blockIdx.x * OB_ROWS;
    for (int i = tid; i < OB_ROWS * (D / 4); i += 128) {
        int r = i >> 4, q = i & 15;
        int gr = row0 + r;
        int grc = gr < N_NODES ? gr : N_NODES - 1;
        float4 a = *((const float4*)(g_acc + (size_t)grc * D) + q);
        xs[r][q * 4 + 0] = a.x;
        xs[r][q * 4 + 1] = a.y;
        xs[r][q * 4 + 2] = a.z;
        xs[r][q * 4 + 3] = a.w;
    }
    __syncthreads();

    int tx = tid & 7;        // col octet
    int ty = tid >> 3;       // row octet

    ull acc[8][4];
    {
        ulonglong2 b01 = *(const ulonglong2*)&bs[tx * 8];
        ulonglong2 b23 = *(const ulonglong2*)&bs[tx * 8 + 4];
#pragma unroll
        for (int rr = 0; rr < 8; rr++) {
            acc[rr][0] = b01.x; acc[rr][1] = b01.y;
            acc[rr][2] = b23.x; acc[rr][3] = b23.y;
        }
    }

#pragma unroll 4
    for (int k = 0; k < D; k++) {
        ulonglong2 w01 = *(const ulonglong2*)&Wt[k][tx * 8];
        ulonglong2 w23 = *(const ulonglong2*)&Wt[k][tx * 8 + 4];
#pragma unroll
        for (int rr = 0; rr < 8; rr++) {
            float xv = xs[ty * 8 + rr][k];
            ull xp = pack_f2(xv, xv);
            acc[rr][0] = fma_f2(xp, w01.x, acc[rr][0]);
            acc[rr][1] = fma_f2(xp, w01.y, acc[rr][1]);
            acc[rr][2] = fma_f2(xp, w23.x, acc[rr][2]);
            acc[rr][3] = fma_f2(xp, w23.y, acc[rr][3]);
        }
    }

#pragma unroll
    for (int rr = 0; rr < 8; rr++) {
        int gr = row0 + ty * 8 + rr;
        if (gr < N_NODES) {
            float o[8];
#pragma unroll
            for (int p = 0; p < 4; p++) unpack_f2(acc[rr][p], o[2 * p], o[2 * p + 1]);
#pragma unroll
            for (int q = 0; q < 8; q++) o[q] = o[q] > 0.f ? o[q] : 0.01f * o[q];
            float* dst = out + (size_t)gr * D + tx * 8;
            ((float4*)dst)[0] = make_float4(o[0], o[1], o[2], o[3]);
            ((float4*)dst)[1] = make_float4(o[4], o[5], o[6], o[7]);
        }
    }
}

// ---------------------------------------------------------------------------
// kernel_launch — 3 launches
// ---------------------------------------------------------------------------
extern "C" void kernel_launch(void* const* d_in, const int* in_sizes, int n_in,
                              void* d_out, int out_size) {
    const float* embed  = (const float*)d_in[0];
    const int*   src    = (const int*)d_in[1];
    const int*   dst    = (const int*)d_in[2];
    const float* ew     = (const float*)d_in[3];
    const float* outdeg = (const float*)d_in[4];
    const float* indeg  = (const float*)d_in[5];
    const float* W      = (const float*)d_in[6];
    const float* b      = (const float*)d_in[7];
    float* out = (float*)d_out;

    {   // 1. fused fp16 prep + bucket scatter (2 edges/thread)
        int threads = 256;
        int blocks = (N_EDGES / 2 + threads - 1) / threads;   // 1563
        prep_scatter_kernel<<<blocks, threads>>>(embed, src, dst, ew, outdeg);
    }
    {   // 2. gather-accumulate (8 lanes/node, fused embed add)
        int total = N_NODES * 8;
        int threads = 256;
        int blocks = (total + threads - 1) / threads;         // 1563
        accum_kernel<<<blocks, threads>>>(embed, indeg);
    }
    {   // 3. tiled GEMM + LeakyReLU
        int blocks = (N_NODES + OB_ROWS - 1) / OB_ROWS;       // 391
        out_kernel<<<blocks, 128>>>(W, b, out);
    }
}